// round 17
// baseline (speedup 1.0000x reference)
#include <cuda_runtime.h>
#include <cuda_bf16.h>
#include <cstdint>

#define D  768
#define KP 256

__device__ __align__(16) uint8_t g_pn8[KP * D];    // normalized prototypes e4m3 [k][d]
__device__ __align__(16) uint8_t g_pwt8[D * KP];   // e4m3( (P@W^T)[k][e] * 64 ) : [e][k]
__device__ __align__(16) float   g_pwCp[4 * D];    // C partials per k-group

// ---------------------------------------------------------------------------
__device__ __forceinline__ uint32_t smem_u32(const void* p) {
    uint32_t a;
    asm("{ .reg .u64 t; cvta.to.shared.u64 t, %1; cvt.u32.u64 %0, t; }" : "=r"(a) : "l"(p));
    return a;
}
__device__ __forceinline__ uint16_t packe4m3(float lo, float hi) {
    uint16_t h;
    asm("cvt.rn.satfinite.e4m3x2.f32 %0, %1, %2;" : "=h"(h) : "f"(hi), "f"(lo));
    return h;
}
__device__ __forceinline__ void ldsm_x4(uint32_t& r0, uint32_t& r1, uint32_t& r2, uint32_t& r3,
                                        uint32_t addr) {
    asm volatile("ldmatrix.sync.aligned.m8n8.x4.shared.b16 {%0,%1,%2,%3}, [%4];"
                 : "=r"(r0), "=r"(r1), "=r"(r2), "=r"(r3) : "r"(addr));
}
__device__ __forceinline__ void mma8(float* c, uint32_t a0, uint32_t a1, uint32_t a2, uint32_t a3,
                                     uint32_t b0, uint32_t b1) {
    asm volatile(
        "mma.sync.aligned.m16n8k32.row.col.f32.e4m3.e4m3.f32 "
        "{%0,%1,%2,%3}, {%4,%5,%6,%7}, {%8,%9}, {%0,%1,%2,%3};"
        : "+f"(c[0]), "+f"(c[1]), "+f"(c[2]), "+f"(c[3])
        : "r"(a0), "r"(a1), "r"(a2), "r"(a3), "r"(b0), "r"(b1));
}
#define CP16(dst, src) asm volatile("cp.async.cg.shared.global [%0], [%1], 16;" :: "r"(dst), "l"(src))
#define CP_COMMIT()    asm volatile("cp.async.commit_group;" ::: "memory")
#define CP_WAIT0()     asm volatile("cp.async.wait_group 0;" ::: "memory")

// ---------------------------------------------------------------------------
// Prep v3 (unchanged from R16): [0,256) prototypes -> e4m3;
//          [256,448): PWT e4m3(x64), 48 e-groups x 4 k-groups + C partials
// ---------------------------------------------------------------------------
__global__ void prep_kernel(const float* __restrict__ P, const float* __restrict__ W) {
    __shared__ float Pt[64 * 33];
    __shared__ float Wt[16 * 33 + 8];
    __shared__ float Rd[8][4];
    const int tid = threadIdx.x;
    if (blockIdx.x < 256) {
        float* red = Pt;
        int k = blockIdx.x;
        const float* row = P + k * D;
        float s = 0.f;
        for (int d = tid; d < D; d += 256) { float v = row[d]; s += v * v; }
#pragma unroll
        for (int o = 16; o; o >>= 1) s += __shfl_xor_sync(0xffffffffu, s, o);
        if ((tid & 31) == 0) red[tid >> 5] = s;
        __syncthreads();
        if (tid == 0) {
            float t = 0.f;
#pragma unroll
            for (int i = 0; i < 8; ++i) t += red[i];
            red[0] = 1.f / fmaxf(sqrtf(t), 1e-12f);
        }
        __syncthreads();
        float iv = red[0];
        for (int p = tid; p < D / 2; p += 256) {
            uint16_t h = packe4m3(row[2 * p] * iv, row[2 * p + 1] * iv);
            *reinterpret_cast<uint16_t*>(g_pn8 + k * D + 2 * p) = h;
        }
    } else {
        const int bid = blockIdx.x - 256;
        const int eg = bid >> 2, kg = bid & 3;
        const int e0 = eg * 16, k0 = kg * 64;
        const int kk = tid & 63, esub = tid >> 6;
        float a[4] = {0.f, 0.f, 0.f, 0.f};
        for (int dc = 0; dc < D; dc += 32) {
#pragma unroll
            for (int it = 0; it < 8; ++it) {
                int idx = tid + 256 * it;
                int row = idx >> 5, d = idx & 31;
                Pt[row * 33 + d] = P[(k0 + row) * D + dc + d];
            }
#pragma unroll
            for (int it = 0; it < 2; ++it) {
                int idx = tid + 256 * it;
                int e = idx >> 5, d = idx & 31;
                Wt[e * 33 + d] = W[(e0 + e) * D + dc + d];
            }
            __syncthreads();
#pragma unroll
            for (int d = 0; d < 32; ++d) {
                float p = Pt[kk * 33 + d];
                a[0] += p * Wt[(esub * 4 + 0) * 33 + d];
                a[1] += p * Wt[(esub * 4 + 1) * 33 + d];
                a[2] += p * Wt[(esub * 4 + 2) * 33 + d];
                a[3] += p * Wt[(esub * 4 + 3) * 33 + d];
            }
            __syncthreads();
        }
#pragma unroll
        for (int i = 0; i < 4; ++i)
            g_pwt8[(e0 + esub * 4 + i) * KP + (k0 + kk)] =
                (uint8_t)(packe4m3(a[i] * 64.f, 0.f) & 0xff);
        const int w = tid >> 5;
#pragma unroll
        for (int i = 0; i < 4; ++i) {
            float s = a[i];
#pragma unroll
            for (int o = 16; o; o >>= 1) s += __shfl_xor_sync(0xffffffffu, s, o);
            if ((tid & 31) == 0) Rd[w][i] = s;
        }
        __syncthreads();
        if (tid < 16) {
            int es = tid >> 2, i = tid & 3;
            g_pwCp[kg * D + e0 + es * 4 + i] = Rd[es * 2][i] + Rd[es * 2 + 1][i];
        }
    }
}

// ---------------------------------------------------------------------------
// Main kernel: 3 CTAs/SM. M_TILE=64 processed as two 32-row halves.
// ---------------------------------------------------------------------------
#define OFF_INV   0            // float[64]
#define OFF_INVS  256          // float[64]
#define OFF_PARTS 512          // float[8][32] = 1024
#define OFF_EXP   1536         // e4m3 d-tile [64][272B] = 17408 -> 18944
#define OFF_XF    18944        // e4m3 [32][768] swizzled = 24576 -> 43520
#define OFF_PN    43520        // e4m3 [256][80] = 20480 -> 64000
#define SMEM_MAIN 64000
// phase-3 overlay (XF+PN region dead):
#define OFF_PW    18944        // e4m3 [128][272B] = 34816 -> 53760
#define OFF_C     53760        // float[768]
#define OFF_B     56832        // float[768] -> 59904

__device__ __forceinline__ void stage_xf(char* smem, const float* xhalf, int tid,
                                         float* inv, int h) {
    const int sr = tid >> 3, sc = tid & 7;
    const float* src = xhalf + sr * D;
    float sq = 0.f;
#pragma unroll 8
    for (int f = 0; f < 24; ++f) {
        int w4 = sc + 8 * f;
        float4 v = *reinterpret_cast<const float4*>(src + w4 * 4);
        sq += v.x * v.x + v.y * v.y + v.z * v.z + v.w * v.w;
        uint32_t word = (uint32_t)packe4m3(v.x, v.y) | ((uint32_t)packe4m3(v.z, v.w) << 16);
        uint32_t addr = OFF_XF + sr * 768 + (((w4 >> 2) ^ (sr & 7)) << 4) + ((w4 & 3) << 2);
        *reinterpret_cast<uint32_t*>(smem + addr) = word;
    }
    sq += __shfl_xor_sync(0xffffffffu, sq, 1);
    sq += __shfl_xor_sync(0xffffffffu, sq, 2);
    sq += __shfl_xor_sync(0xffffffffu, sq, 4);
    if (sc == 0) inv[h * 32 + sr] = 1.f / fmaxf(sqrtf(sq), 1e-12f);
}

__device__ __forceinline__ void softmax_half(char* smem, float acc[2][4][4],
                                             const float* inv, float* parts,
                                             int h, int w, int g, int q) {
#pragma unroll
    for (int mt = 0; mt < 2; ++mt) {
        const int r0 = mt * 16 + g, r1 = r0 + 8;
        const float iv0 = inv[h * 32 + r0], iv1 = inv[h * 32 + r1];
        float s0 = 0.f, s1 = 0.f;
#pragma unroll
        for (int nt = 0; nt < 4; ++nt) {
            float e0 = __expf(acc[mt][nt][0] * iv0);
            float e1 = __expf(acc[mt][nt][1] * iv0);
            float e2 = __expf(acc[mt][nt][2] * iv1);
            float e3 = __expf(acc[mt][nt][3] * iv1);
            const uint32_t cb = w * 32 + nt * 8 + 2 * q;
            *reinterpret_cast<uint16_t*>(smem + OFF_EXP + (h * 32 + r0) * 272 + cb) =
                packe4m3(64.f * (e0 - 1.f), 64.f * (e1 - 1.f));
            *reinterpret_cast<uint16_t*>(smem + OFF_EXP + (h * 32 + r1) * 272 + cb) =
                packe4m3(64.f * (e2 - 1.f), 64.f * (e3 - 1.f));
            s0 += e0 + e1; s1 += e2 + e3;
        }
        s0 += __shfl_xor_sync(0xffffffffu, s0, 1);
        s0 += __shfl_xor_sync(0xffffffffu, s0, 2);
        s1 += __shfl_xor_sync(0xffffffffu, s1, 1);
        s1 += __shfl_xor_sync(0xffffffffu, s1, 2);
        if (q == 0) { parts[w * 32 + r0] = s0; parts[w * 32 + r1] = s1; }
    }
}

__global__ __launch_bounds__(256, 3)
void main_kernel(const float* __restrict__ x, const float* __restrict__ bias,
                 float* __restrict__ out) {
    extern __shared__ char smem[];
    const uint32_t sb = smem_u32(smem);
    const int tid = threadIdx.x, w = tid >> 5, lane = tid & 31;
    const int g = lane >> 2, q = lane & 3;
    const long m0 = (long)blockIdx.x * 64;

    float* inv   = reinterpret_cast<float*>(smem + OFF_INV);
    float* invS  = reinterpret_cast<float*>(smem + OFF_INVS);
    float* parts = reinterpret_cast<float*>(smem + OFF_PARTS);
    float* Cs    = reinterpret_cast<float*>(smem + OFF_C);
    float* Bs    = reinterpret_cast<float*>(smem + OFF_B);

    // ---- phase-1 per-thread constants ----
    const uint32_t s7 = lane & 7;                            // XF swizzle key (both mt)
    const uint32_t ua = (lane >> 4) & 1;
    uint32_t abase[2];
#pragma unroll
    for (int mt = 0; mt < 2; ++mt)
        abase[mt] = OFF_XF + (mt * 16 + (lane & 7) + ((lane >> 3) & 1) * 8) * 768;
    const uint32_t boff1 = (w * 32 + (lane & 7) + ((lane >> 4) & 1) * 8) * 80 + ((lane >> 3) & 1) * 16;
    const int pr = tid >> 2, pu = tid & 3;                   // PN prefetch decomposition

    float acc[2][4][4];
#pragma unroll
    for (int mt = 0; mt < 2; ++mt)
#pragma unroll
        for (int nt = 0; nt < 4; ++nt)
#pragma unroll
            for (int j = 0; j < 4; ++j) acc[mt][nt][j] = 0.f;

    // ---- prologue: stage XF half 0, prefetch PN chunk 0 into regs ----
    stage_xf(smem, x + m0 * D, tid, inv, 0);
    uint4 Preg[4];
#pragma unroll
    for (int it = 0; it < 4; ++it)
        Preg[it] = *reinterpret_cast<const uint4*>(g_pn8 + (pr + 64 * it) * D + pu * 16);

    // ---- Phase 1: 24 iterations (2 halves x 12 K-chunks of 64) ----
#pragma unroll 1
    for (int i = 0; i < 24; ++i) {
        const int c = (i < 12) ? i : i - 12;
        // publish PN chunk c from regs
#pragma unroll
        for (int it = 0; it < 4; ++it)
            *reinterpret_cast<uint4*>(smem + OFF_PN + (pr + 64 * it) * 80 + pu * 16) = Preg[it];
        // prefetch next chunk (latency spans MMA)
        if (i < 23) {
            const int cn = (c == 11) ? 0 : c + 1;
#pragma unroll
            for (int it = 0; it < 4; ++it)
                Preg[it] = *reinterpret_cast<const uint4*>(
                    g_pn8 + (pr + 64 * it) * D + cn * 64 + pu * 16);
        }
        __syncthreads();          // PN(c) + (XF at half start) visible
        // MMA chunk c: warp tile 32 rows x cols [w*32, w*32+32)
#pragma unroll
        for (int ks = 0; ks < 2; ++ks) {
            uint32_t a0[2], a1[2], a2[2], a3[2];
#pragma unroll
            for (int mt = 0; mt < 2; ++mt) {
                uint32_t u = (uint32_t)(c * 4 + ks * 2) + ua;
                ldsm_x4(a0[mt], a1[mt], a2[mt], a3[mt],
                        sb + abase[mt] + ((u ^ s7) << 4));
            }
#pragma unroll
            for (int p = 0; p < 2; ++p) {
                uint32_t b0, b1, b2, b3;
                ldsm_x4(b0, b1, b2, b3, sb + OFF_PN + boff1 + p * 16 * 80 + ks * 32);
#pragma unroll
                for (int mt = 0; mt < 2; ++mt) {
                    mma8(acc[mt][2 * p],     a0[mt], a1[mt], a2[mt], a3[mt], b0, b1);
                    mma8(acc[mt][2 * p + 1], a0[mt], a1[mt], a2[mt], a3[mt], b2, b3);
                }
            }
        }
        __syncthreads();          // MMA reads done: PN buffer free; at i=11 XF free too
        if (i == 11) {
            // half boundary: softmax rows 0..31, restage XF with rows 32..63
            softmax_half(smem, acc, inv, parts, 0, w, g, q);
#pragma unroll
            for (int mt = 0; mt < 2; ++mt)
#pragma unroll
                for (int nt = 0; nt < 4; ++nt)
#pragma unroll
                    for (int j = 0; j < 4; ++j) acc[mt][nt][j] = 0.f;
            stage_xf(smem, x + (m0 + 32) * D, tid, inv, 1);
            __syncthreads();      // parts/XF/inv visible
            if (tid < 32) {
                float s = 0.f;
#pragma unroll
                for (int ww = 0; ww < 8; ++ww) s += parts[ww * 32 + tid];
                invS[tid] = 1.f / (256.f * s);
            }
        }
    }

    // ---- softmax half 1 + phase-3 staging ----
    softmax_half(smem, acc, inv, parts, 1, w, g, q);
#pragma unroll
    for (int i2 = 0; i2 < 3; ++i2) {
        int e = tid + 256 * i2;
        Cs[e] = g_pwCp[e] + g_pwCp[D + e] + g_pwCp[2 * D + e] + g_pwCp[3 * D + e];
        Bs[e] = bias[e];
    }
#pragma unroll
    for (int it = 0; it < 8; ++it) {
        int idx = tid + 256 * it;
        int row = idx >> 4, u2 = idx & 15;
        CP16(sb + OFF_PW + row * 272 + u2 * 16, g_pwt8 + row * KP + u2 * 16);
    }
    CP_COMMIT();
    __syncthreads();
    if (tid < 32) {
        float s = 0.f;
#pragma unroll
        for (int ww = 0; ww < 8; ++ww) s += parts[ww * 32 + tid];
        invS[32 + tid] = 1.f / (256.f * s);
    }

    // ---- Phase 3 (FP8 d-decomp): 6 e-chunks of 128, single PW buffer ----
    const int wm3 = w & 1, wn3 = w >> 1;
    const uint32_t aoff3 = (wm3 * 32 + (lane & 7) + ((lane >> 3) & 1) * 8) * 272 + ((lane >> 4) & 1) * 16;
    const uint32_t boff3 = (wn3 * 32 + (lane & 7) + ((lane >> 4) & 1) * 8) * 272 + ((lane >> 3) & 1) * 16;
    const float inv4096 = 1.f / 4096.f;

    for (int j = 0; j < 6; ++j) {
        CP_WAIT0();
        __syncthreads();                  // PW(j) ready; invS visible at j=0

        float acc2[2][4][4];
#pragma unroll
        for (int mt = 0; mt < 2; ++mt)
#pragma unroll
            for (int nt = 0; nt < 4; ++nt)
#pragma unroll
                for (int jj = 0; jj < 4; ++jj) acc2[mt][nt][jj] = 0.f;

#pragma unroll
        for (int ks = 0; ks < 8; ++ks) {
            uint32_t b0, b1, b2, b3, b4, b5, b6, b7;
            ldsm_x4(b0, b1, b2, b3, sb + OFF_PW + boff3 + ks * 32);
            ldsm_x4(b4, b5, b6, b7, sb + OFF_PW + boff3 + 16 * 272 + ks * 32);
#pragma unroll
            for (int mt = 0; mt < 2; ++mt) {
                uint32_t a0, a1, a2, a3;
                ldsm_x4(a0, a1, a2, a3, sb + OFF_EXP + aoff3 + mt * 16 * 272 + ks * 32);
                mma8(acc2[mt][0], a0, a1, a2, a3, b0, b1);
                mma8(acc2[mt][1], a0, a1, a2, a3, b2, b3);
                mma8(acc2[mt][2], a0, a1, a2, a3, b4, b5);
                mma8(acc2[mt][3], a0, a1, a2, a3, b6, b7);
            }
        }
        __syncthreads();                  // PW reads done
        if (j < 5) {
#pragma unroll
            for (int it = 0; it < 8; ++it) {
                int idx = tid + 256 * it;
                int row = idx >> 4, u2 = idx & 15;
                CP16(sb + OFF_PW + row * 272 + u2 * 16,
                     g_pwt8 + ((j + 1) * 128 + row) * KP + u2 * 16);
            }
            CP_COMMIT();
        }
        // epilogue: out = (C + corr/4096) * invS + bias
#pragma unroll
        for (int mt = 0; mt < 2; ++mt) {
            const int r0 = wm3 * 32 + mt * 16 + g, r1 = r0 + 8;
            const float is0 = invS[r0], is1 = invS[r1];
#pragma unroll
            for (int nt = 0; nt < 4; ++nt) {
                const int cc = j * 128 + wn3 * 32 + nt * 8 + 2 * q;
                const float2 bv = *reinterpret_cast<const float2*>(Bs + cc);
                const float2 Cv = *reinterpret_cast<const float2*>(Cs + cc);
                *reinterpret_cast<float2*>(out + (m0 + r0) * D + cc) = make_float2(
                    (Cv.x + acc2[mt][nt][0] * inv4096) * is0 + bv.x,
                    (Cv.y + acc2[mt][nt][1] * inv4096) * is0 + bv.y);
                *reinterpret_cast<float2*>(out + (m0 + r1) * D + cc) = make_float2(
                    (Cv.x + acc2[mt][nt][2] * inv4096) * is1 + bv.x,
                    (Cv.y + acc2[mt][nt][3] * inv4096) * is1 + bv.y);
            }
        }
    }
}

// ---------------------------------------------------------------------------
extern "C" void kernel_launch(void* const* d_in, const int* in_sizes, int n_in,
                              void* d_out, int out_size) {
    const float* x = (const float*)d_in[0];
    const float* P = (const float*)d_in[1];
    const float* W = (const float*)d_in[2];
    const float* b = (const float*)d_in[3];
    float* out = (float*)d_out;

    cudaFuncSetAttribute(main_kernel, cudaFuncAttributeMaxDynamicSharedMemorySize, SMEM_MAIN);

    prep_kernel<<<448, 256>>>(P, W);

    int rows = in_sizes[0] / D;               // 131072
    main_kernel<<<rows / 64, 256, SMEM_MAIN>>>(x, b, out);
}